// round 11
// baseline (speedup 1.0000x reference)
#include <cuda_runtime.h>

#define BATCH 16
#define ANCH 22743
#define ROW 85
#define NCLS 80
#define NSC (ANCH * NCLS)
#define ABLK 89            // ceil(ANCH / 256) scan blocks per image
#define PRE 1000
#define MAXDET 300
#define CONF_THRESH 0.2f
#define PRE_THRESH 0.9f
#define NMS_THRESH 0.45f
#define MAXK 64
#define FULLM 0xffffffffu

// fast-path fine bins over (0.9, 1.0): (bits - bits(0.9f)) >> 9
#define B9OFF 0x3F666666u
#define NBF 4096
#define GRPF 4             // NBF / 1024
#define CAPB 32

// slow-path histogram over (0.2, 1.0): (bits - 0x3E000000) >> 12
#define NBS 6144
#define B2OFF 0x3E000000u
#define GRPS 6             // NBS / 1024
#define SORTN 2048

// ---------------- device scratch (static; no allocations) ----------------
__device__ unsigned long long g_bkey[BATCH][NBF][CAPB];
__device__ float4 g_bbox[BATCH][NBF][CAPB];
__device__ int g_bincnt[BATCH][NBF];  // zero at load; final re-zeroes each run
__device__ int g_done[BATCH];         // scan-block completion counters

struct SMF {
    unsigned long long skeys[1024];   // rank-ordered top-1000 keys
    int cntF[NBF];                    // fast bin counts
    int baseF[NBF];                   // fast bin rank bases (suffix(bin+1))
    int rsum[1024];                   // group suffix sums (shared fast/slow)
    int wred[33];
    // slow-path only:
    int histS[NBS];
    int bposS[NBS];
    unsigned long long keysS[SORTN];
    // common tail state:
    float rbx1[1024], rby1[1024], rbx2[1024], rby2[1024];
    float sx1[1024], sy1[1024], sx2[1024], sy2[1024], sar[1024];
    float ssc[1024];
    int slb[1024];
    int clist[NCLS * MAXK];
    int wcnt[32 * NCLS];
    int wof[32 * NCLS];
    int ccnt[NCLS];
    int keepf[1024];
    int wscan[33];
    int over, cstar, smax;
};

// Scan: conf>0.9 prefilter, warp-cooperative scoring, bin-scatter s>0.9
// candidates (key + box) into fine global bins. Per-image done counter.
__global__ void scan_kernel(const float* __restrict__ preds) {
    cudaTriggerProgrammaticLaunchCompletion();
    int b = blockIdx.y;
    int a0 = blockIdx.x * 256 + threadIdx.x;
    int lane = threadIdx.x & 31;
    bool inb = a0 < ANCH;
    float conf0 = inb ? preds[((size_t)b * ANCH + a0) * ROW + 4] : 0.0f;
    unsigned m = __ballot_sync(FULLM, inb && (conf0 > PRE_THRESH));
    while (m) {
        int src = __ffs(m) - 1;
        m &= m - 1;
        int a = __shfl_sync(FULLM, a0, src);
        float conf = __shfl_sync(FULLM, conf0, src);
        const float* row = preds + ((size_t)b * ANCH + a) * ROW;
#pragma unroll
        for (int part = 0; part < 3; part++) {
            int k = part * 32 + lane;
            float p = (k < NCLS) ? row[5 + k] : 0.0f;
            float s = __fmul_rn(p, conf);
            if (k < NCLS && s > PRE_THRESH) {
                unsigned sb = __float_as_uint(s);
                int bin = min((int)((sb - B9OFF) >> 9), NBF - 1);
                int slot = atomicAdd(&g_bincnt[b][bin], 1);
                if (slot < CAPB) {
                    unsigned flat = (unsigned)a * 80u + (unsigned)k;
                    g_bkey[b][bin][slot] =
                        ((unsigned long long)sb << 32) |
                        (unsigned long long)(~flat);
                    g_bbox[b][bin][slot] =
                        make_float4(row[0], row[1], row[2], row[3]);
                }
            }
        }
    }
    __threadfence();
    __syncthreads();
    if (threadIdx.x == 0) atomicAdd(&g_done[b], 1);
}

// Inclusive suffix sums over grp-bucket groups of histArr -> sm.rsum
__device__ __forceinline__ void compute_suffix(SMF& sm, const int* histArr,
                                               int grp, int tid, int lane,
                                               int wid) {
    int v = 0;
    for (int q = 0; q < grp; q++) v += histArr[tid * grp + q];
    int vs = v;
#pragma unroll
    for (int off = 1; off < 32; off <<= 1) {
        int t = __shfl_down_sync(FULLM, vs, off);
        if (lane + off < 32) vs += t;
    }
    if (lane == 0) sm.wred[wid] = vs;
    __syncthreads();
    if (wid == 0) {
        int w = sm.wred[lane];
        __syncwarp();
#pragma unroll
        for (int off = 1; off < 32; off <<= 1) {
            int t = __shfl_down_sync(FULLM, w, off);
            if (lane + off < 32) w += t;
        }
        sm.wred[lane] = w;  // inclusive suffix over warp totals
    }
    __syncthreads();
    sm.rsum[tid] = vs + ((wid < 31) ? sm.wred[wid + 1] : 0);
    __syncthreads();
}

__global__ void __launch_bounds__(1024, 1)
final_kernel(const float* __restrict__ preds, float* __restrict__ out) {
    extern __shared__ char smc[];
    SMF& sm = *(SMF*)smc;
    int b = blockIdx.x;
    int tid = threadIdx.x;
    int lane = tid & 31;
    int wid = tid >> 5;

    // ---- dependency-free init ----
    sm.skeys[tid] = 0ull;
    for (int i = tid; i < 32 * NCLS; i += 1024) sm.wcnt[i] = 0;
    sm.keepf[tid] = 0;
    if (tid == 0) { sm.over = 0; sm.cstar = 0x7fffffff; sm.smax = 0; }

    // ---- wait for THIS image's scan blocks (flag protocol) ----
    if (tid == 0) {
        while (atomicAdd(&g_done[b], 0) < ABLK) {}
        g_done[b] = 0;
        __threadfence();
    }
    __syncthreads();

    // ---- ingest bin counts (4/thread), re-zero, detect overflow ----
    {
        bool ov = false;
#pragma unroll
        for (int q = 0; q < GRPF; q++) {
            int i = tid * GRPF + q;
            int v = g_bincnt[b][i];
            sm.cntF[i] = v;
            g_bincnt[b][i] = 0;
            ov |= (v > CAPB);
        }
        if (ov) atomicOr(&sm.over, 1);
    }
    __syncthreads();

    // ---- fast suffix sums over 4-bin groups ----
    compute_suffix(sm, sm.cntF, GRPF, tid, lane, wid);
    bool slow = (sm.rsum[0] < PRE) || sm.over;

    if (!slow) {
        int t_target = PRE;
        // cutoff + per-bin rank bases
        if (sm.rsum[tid] >= t_target &&
            (tid == 1023 || sm.rsum[tid + 1] < t_target)) {
            int acc = (tid < 1023) ? sm.rsum[tid + 1] : 0;
            for (int bk = tid * GRPF + GRPF - 1; bk >= tid * GRPF; bk--) {
                acc += sm.cntF[bk];
                if (acc >= t_target) { sm.cstar = bk; break; }
            }
        }
        {
            int run = (tid < 1023) ? sm.rsum[tid + 1] : 0;
#pragma unroll
            for (int q = GRPF - 1; q >= 0; q--) {
                sm.baseF[tid * GRPF + q] = run;   // suffix(bin+1)
                run += sm.cntF[tid * GRPF + q];
            }
        }
        __syncthreads();
        int cs = sm.cstar;

        // ---- rank-direct: warp per bin, lane per slot (cnt <= 32) ----
        unsigned lmxb = 0;
        for (int bin = cs + wid; bin < NBF; bin += 32) {
            int cnt = sm.cntF[bin];              // warp-uniform
            if (cnt == 0) continue;
            unsigned long long k =
                (lane < cnt) ? g_bkey[b][bin][lane] : 0ull;
            int r = 0;
            for (int j = 0; j < cnt; j++) {
                unsigned long long kj = __shfl_sync(FULLM, k, j);
                r += (kj > k);
            }
            int rank = sm.baseF[bin] + r;
            if (lane < cnt && rank < PRE) {
                sm.skeys[rank] = k;
                float4 bx = g_bbox[b][bin][lane];
                sm.rbx1[rank] = bx.x; sm.rby1[rank] = bx.y;
                sm.rbx2[rank] = bx.z; sm.rby2[rank] = bx.w;
                float mx = fmaxf(fmaxf(bx.x, bx.y), fmaxf(bx.z, bx.w));
                unsigned mb = (unsigned)__float_as_int(mx);  // coords >= 0
                lmxb = max(lmxb, mb);
            }
        }
#pragma unroll
        for (int off = 16; off > 0; off >>= 1)
            lmxb = max(lmxb, __shfl_xor_sync(FULLM, lmxb, off));
        if (lane == 0) atomicMax(&sm.smax, (int)lmxb);
        __syncthreads();
    } else {
        // ================= slow path (statistically never taken) ========
#pragma unroll
        for (int q = 0; q < GRPS; q++) sm.histS[tid * GRPS + q] = 0;
        __syncthreads();
        const float* bp = preds + (size_t)b * ANCH * ROW;
        for (int i = tid; i < NSC; i += 1024) {
            int a = i / 80, k = i - a * 80;
            float s = __fmul_rn(bp[(size_t)a * ROW + 5 + k],
                                bp[(size_t)a * ROW + 4]);
            if (s > CONF_THRESH) {
                int bk = min((int)((__float_as_uint(s) - B2OFF) >> 12), NBS - 1);
                atomicAdd(&sm.histS[bk], 1);
            }
        }
        __syncthreads();
        compute_suffix(sm, sm.histS, GRPS, tid, lane, wid);
        int t_target = min(PRE, sm.rsum[0]);
        if (t_target > 0 && sm.rsum[tid] >= t_target &&
            (tid == 1023 || sm.rsum[tid + 1] < t_target)) {
            int acc = (tid < 1023) ? sm.rsum[tid + 1] : 0;
            for (int bk = tid * GRPS + GRPS - 1; bk >= tid * GRPS; bk--) {
                acc += sm.histS[bk];
                if (acc >= t_target) { sm.cstar = bk; break; }
            }
        }
        {
            int run = (tid < 1023) ? sm.rsum[tid + 1] : 0;
            for (int q = GRPS - 1; q >= 0; q--) {
                sm.bposS[tid * GRPS + q] = run;
                run += sm.histS[tid * GRPS + q];
            }
        }
        __syncthreads();
        int cs = sm.cstar;
        for (int i = tid; i < NSC; i += 1024) {
            int a = i / 80, k = i - a * 80;
            float s = __fmul_rn(bp[(size_t)a * ROW + 5 + k],
                                bp[(size_t)a * ROW + 4]);
            if (s > CONF_THRESH) {
                int bk = min((int)((__float_as_uint(s) - B2OFF) >> 12), NBS - 1);
                if (bk >= cs) {
                    int pos = atomicAdd(&sm.bposS[bk], 1);
                    if (pos < SORTN)
                        sm.keysS[pos] =
                            ((unsigned long long)__float_as_uint(s) << 32) |
                            (unsigned long long)(~(unsigned)i);
                }
            }
        }
        __syncthreads();
        {
            int mC = min(sm.rsum[0], SORTN);
#pragma unroll
            for (int it = 0; it < 2; it++) {
                int idx = tid + it * 1024;
                if (idx < mC) {
                    unsigned long long key = sm.keysS[idx];
                    int bk = min((int)(((unsigned)(key >> 32) - B2OFF) >> 12),
                                 NBS - 1);
                    int endv = sm.bposS[bk];
                    int base = endv - sm.histS[bk];
                    int end = min(endv, SORTN);
                    int rank = base;
                    for (int j = base; j < end; j++)
                        rank += (sm.keysS[j] > key);
                    if (rank < PRE) {
                        sm.skeys[rank] = key;
                        unsigned flat = ~((unsigned)(key & 0xffffffffull));
                        const float* row = bp + (size_t)(flat / 80u) * ROW;
                        float b0 = row[0], b1 = row[1];
                        float b2 = row[2], b3 = row[3];
                        sm.rbx1[rank] = b0; sm.rby1[rank] = b1;
                        sm.rbx2[rank] = b2; sm.rby2[rank] = b3;
                        float mx = fmaxf(fmaxf(b0, b1), fmaxf(b2, b3));
                        atomicMax(&sm.smax, __float_as_int(mx));
                    }
                }
            }
        }
        __syncthreads();
    }

    // ---- decode top-1000: score/label ----
    {
        unsigned long long key = (tid < PRE) ? sm.skeys[tid] : 0ull;
        float sc = -1.0f;
        unsigned flat = 0u;
        if (tid < PRE && key != 0ull) {
            sc = __uint_as_float((unsigned)(key >> 32));
            flat = ~((unsigned)(key & 0xffffffffull));
        }
        unsigned lbl = flat - (flat / 80u) * 80u;
        sm.ssc[tid] = sc;
        sm.slb[tid] = (int)lbl;
    }
    __syncthreads();

    // ---- class shift (bit-exact reference arithmetic) ----
    {
        float M = __int_as_float(sm.smax);
        float shb = __fadd_rn(M, 1.0f);
        float sh = __fmul_rn((float)sm.slb[tid], shb);
        float x1 = __fadd_rn(sm.rbx1[tid], sh);
        float y1 = __fadd_rn(sm.rby1[tid], sh);
        float x2 = __fadd_rn(sm.rbx2[tid], sh);
        float y2 = __fadd_rn(sm.rby2[tid], sh);
        sm.sx1[tid] = x1; sm.sy1[tid] = y1; sm.sx2[tid] = x2; sm.sy2[tid] = y2;
        sm.sar[tid] = __fmul_rn(fmaxf(__fsub_rn(x2, x1), 0.0f),
                                fmaxf(__fsub_rn(y2, y1), 0.0f));
    }

    // ---- stable per-class grouping: match_any + cross-warp shfl scan ----
    int mylbl = (tid < PRE) ? sm.slb[tid] : -1;
    unsigned grpm = __match_any_sync(FULLM, mylbl);
    int wrank = __popc(grpm & ((1u << lane) - 1u));
    if (tid < PRE && wrank == 0)
        sm.wcnt[wid * NCLS + mylbl] = __popc(grpm);
    __syncthreads();
    for (int c = wid; c < NCLS; c += 32) {
        int v = sm.wcnt[lane * NCLS + c];
        int x = v;
#pragma unroll
        for (int off = 1; off < 32; off <<= 1) {
            int t = __shfl_up_sync(FULLM, x, off);
            if (lane >= off) x += t;
        }
        sm.wof[lane * NCLS + c] = x - v;  // exclusive
        if (lane == 31) sm.ccnt[c] = x;
    }
    __syncthreads();
    if (tid < PRE) {
        int pos = sm.wof[wid * NCLS + mylbl] + wrank;
        if (pos < MAXK) sm.clist[mylbl * MAXK + pos] = tid;
    }
    __syncthreads();

    // ---- warp-parallel per-class greedy NMS (one warp per class) ----
    for (int c = wid; c < NCLS; c += 32) {
        int kc = min(sm.ccnt[c], MAXK);
        if (kc == 0) continue;
        if (kc <= 32) {
            int j1 = (lane < kc) ? sm.clist[c * MAXK + lane] : 0;
            float x1a = sm.sx1[j1], y1a = sm.sy1[j1];
            float x2a = sm.sx2[j1], y2a = sm.sy2[j1], ara = sm.sar[j1];
            unsigned keep =
                __ballot_sync(FULLM, lane < kc && sm.ssc[j1] > CONF_THRESH);
            for (int ii = 0; ii < kc; ii++) {
                if (!((keep >> ii) & 1u)) continue;  // warp-uniform
                float px1 = __shfl_sync(FULLM, x1a, ii);
                float py1 = __shfl_sync(FULLM, y1a, ii);
                float px2 = __shfl_sync(FULLM, x2a, ii);
                float py2 = __shfl_sync(FULLM, y2a, ii);
                float par = __shfl_sync(FULLM, ara, ii);
                float iw = fmaxf(__fsub_rn(fminf(px2, x2a), fmaxf(px1, x1a)), 0.0f);
                float ih = fmaxf(__fsub_rn(fminf(py2, y2a), fmaxf(py1, y1a)), 0.0f);
                float inter = __fmul_rn(iw, ih);
                float den = __fadd_rn(__fsub_rn(__fadd_rn(par, ara), inter), 1e-7f);
                bool s1 = (lane > ii) && (lane < kc) &&
                          (__fdiv_rn(inter, den) > NMS_THRESH);
                keep &= ~__ballot_sync(FULLM, s1);
            }
            if (lane < kc) sm.keepf[j1] = (int)((keep >> lane) & 1u);
        } else {
            int i1 = lane, i2 = lane + 32;
            int j1 = sm.clist[c * MAXK + i1];
            int j2 = (i2 < kc) ? sm.clist[c * MAXK + i2] : 0;
            float x1a = sm.sx1[j1], y1a = sm.sy1[j1];
            float x2a = sm.sx2[j1], y2a = sm.sy2[j1], ara = sm.sar[j1];
            float x1b = sm.sx1[j2], y1b = sm.sy1[j2];
            float x2b = sm.sx2[j2], y2b = sm.sy2[j2], arb = sm.sar[j2];
            unsigned m1 = __ballot_sync(FULLM, sm.ssc[j1] > CONF_THRESH);
            unsigned m2 =
                __ballot_sync(FULLM, i2 < kc && sm.ssc[j2] > CONF_THRESH);
            unsigned long long keep =
                (unsigned long long)m1 | ((unsigned long long)m2 << 32);
            for (int ii = 0; ii < kc; ii++) {
                if (!((keep >> ii) & 1ull)) continue;
                int src = ii & 31;
                bool hi = ii >= 32;
                float px1 = __shfl_sync(FULLM, hi ? x1b : x1a, src);
                float py1 = __shfl_sync(FULLM, hi ? y1b : y1a, src);
                float px2 = __shfl_sync(FULLM, hi ? x2b : x2a, src);
                float py2 = __shfl_sync(FULLM, hi ? y2b : y2a, src);
                float par = __shfl_sync(FULLM, hi ? arb : ara, src);
                float iw1 = fmaxf(__fsub_rn(fminf(px2, x2a), fmaxf(px1, x1a)), 0.0f);
                float ih1 = fmaxf(__fsub_rn(fminf(py2, y2a), fmaxf(py1, y1a)), 0.0f);
                float it1 = __fmul_rn(iw1, ih1);
                float dn1 = __fadd_rn(__fsub_rn(__fadd_rn(par, ara), it1), 1e-7f);
                bool s1 = (i1 > ii) && (__fdiv_rn(it1, dn1) > NMS_THRESH);
                float iw2 = fmaxf(__fsub_rn(fminf(px2, x2b), fmaxf(px1, x1b)), 0.0f);
                float ih2 = fmaxf(__fsub_rn(fminf(py2, y2b), fmaxf(py1, y1b)), 0.0f);
                float it2 = __fmul_rn(iw2, ih2);
                float dn2 = __fadd_rn(__fsub_rn(__fadd_rn(par, arb), it2), 1e-7f);
                bool s2 = (i2 > ii) && (i2 < kc) &&
                          (__fdiv_rn(it2, dn2) > NMS_THRESH);
                unsigned b1 = __ballot_sync(FULLM, s1);
                unsigned b2 = __ballot_sync(FULLM, s2);
                keep &= ~((unsigned long long)b1 |
                          ((unsigned long long)b2 << 32));
            }
            sm.keepf[j1] = (int)((keep >> i1) & 1ull);
            if (i2 < kc) sm.keepf[j2] = (int)((keep >> i2) & 1ull);
        }
    }
    __syncthreads();

    // ---- keep-flag prefix sum (warp shuffles) ----
    int myscan, total;
    {
        int p = sm.keepf[tid];
#pragma unroll
        for (int off = 1; off < 32; off <<= 1) {
            int t = __shfl_up_sync(FULLM, p, off);
            if (lane >= off) p += t;
        }
        if (lane == 31) sm.wscan[wid] = p;
        __syncthreads();
        if (wid == 0) {
            int w = sm.wscan[lane];
            __syncwarp();
#pragma unroll
            for (int off = 1; off < 32; off <<= 1) {
                int t = __shfl_up_sync(FULLM, w, off);
                if (lane >= off) w += t;
            }
            sm.wscan[lane] = w;
        }
        __syncthreads();
        int base = (wid > 0) ? sm.wscan[wid - 1] : 0;
        myscan = base + p;
        total = sm.wscan[31];
    }

    // ---- emit top-300 ----
    float* ob = out;                               // [16][300][4]
    float* os = out + (size_t)BATCH * MAXDET * 4;  // [16][300]
    float* ol = out + (size_t)BATCH * MAXDET * 5;  // [16][300] labels as f32

    if (tid < PRE && sm.keepf[tid]) {
        int m = myscan - 1;
        if (m < MAXDET) {
            float* p = ob + ((size_t)b * MAXDET + m) * 4;
            p[0] = sm.rbx1[tid]; p[1] = sm.rby1[tid];
            p[2] = sm.rbx2[tid]; p[3] = sm.rby2[tid];
            os[b * MAXDET + m] = sm.ssc[tid];
            ol[b * MAXDET + m] = (float)sm.slb[tid];
        }
    }
    for (int m = tid; m < MAXDET; m += 1024) {
        if (m >= total) {
            float* p = ob + ((size_t)b * MAXDET + m) * 4;
            p[0] = 0.0f; p[1] = 0.0f; p[2] = 0.0f; p[3] = 0.0f;
            os[b * MAXDET + m] = 0.0f;
            ol[b * MAXDET + m] = -1.0f;
        }
    }
}

extern "C" void kernel_launch(void* const* d_in, const int* in_sizes, int n_in,
                              void* d_out, int out_size) {
    (void)in_sizes; (void)n_in; (void)out_size;
    const float* preds = (const float*)d_in[0];
    float* out = (float*)d_out;

    cudaFuncSetAttribute(final_kernel,
                         cudaFuncAttributeMaxDynamicSharedMemorySize,
                         (int)sizeof(SMF));

    scan_kernel<<<dim3(ABLK, BATCH), 256>>>(preds);

    // PDL: final may launch early; per-image spin-waits gate real deps
    cudaLaunchConfig_t cfg = {};
    cfg.gridDim = dim3(BATCH, 1, 1);
    cfg.blockDim = dim3(1024, 1, 1);
    cfg.dynamicSmemBytes = sizeof(SMF);
    cfg.stream = 0;
    cudaLaunchAttribute at[1];
    at[0].id = cudaLaunchAttributeProgrammaticStreamSerialization;
    at[0].val.programmaticStreamSerializationAllowed = 1;
    cfg.attrs = at;
    cfg.numAttrs = 1;
    cudaLaunchKernelEx(&cfg, final_kernel, preds, out);
}

// round 12
// speedup vs baseline: 1.3269x; 1.3269x over previous
#include <cuda_runtime.h>

#define BATCH 16
#define ANCH 22743
#define ROW 85
#define NCLS 80
#define NSC (ANCH * NCLS)
#define ABLK 89            // ceil(ANCH / 256)
#define SEGW 1024          // candidate slots per scan block
#define PRE 1000
#define MAXDET 300
#define CONF_THRESH 0.2f
#define PRE_THRESH 0.9f
#define NMS_THRESH 0.45f
#define MAXK 64
#define SORTN 2048
#define FULLM 0xffffffffu

// fast-path bins over (0.9, 1.0): (bits - bits(0.9f)) >> 11, 1024 bins
#define B9OFF 0x3F666666u
#define NBF 1024
// slow-path histogram over (0.2, 1.0): (bits - 0x3E000000) >> 12
#define NBS 6144
#define B2OFF 0x3E000000u
#define GRPS 6             // NBS / 1024

// ---------------- device scratch (static; no allocations) ----------------
__device__ unsigned long long g_cand[BATCH][ABLK * SEGW];
__device__ float4 g_cbox[BATCH][ABLK * SEGW];
__device__ int g_bcnt[BATCH][ABLK];
__device__ int g_hist[BATCH][NBF];   // zero at load; final re-zeroes each run
__device__ int g_ntot[BATCH];
__device__ int g_over[BATCH];

struct SMF {
    unsigned long long keys[SORTN];   // bucket-grouped candidates >= cutoff
    unsigned long long skeys[1024];   // rank-ordered top-1000 keys
    int aux[SORTN];                   // source slot (fast) / flat (slow)
    int histF[NBF];                   // fast bin counts (1 per thread)
    int bposF[NBF];                   // fast bin base, then scatter cursor
    int histS[NBS];                   // slow-path histogram
    int bposS[NBS];
    int rsum[1024];                   // suffix sums (shared fast/slow)
    int wred[33];
    int wcnt[32 * NCLS];
    int wof[32 * NCLS];
    int ccnt[NCLS];
    float rbx1[1024], rby1[1024], rbx2[1024], rby2[1024];
    float sx1[1024], sy1[1024], sx2[1024], sy2[1024], sar[1024];
    float ssc[1024];
    int slb[1024];
    int clist[NCLS * MAXK];
    int keepf[1024];
    int wscan[33];
    int n_tot, over, cstar, mcnt, smax;
};

__device__ __forceinline__ int bucket_fast(unsigned sb) {
    return min((int)((sb - B9OFF) >> 11), NBF - 1);
}
__device__ __forceinline__ int bucket_slow(unsigned sb) {
    return min((int)((sb - B2OFF) >> 12), NBS - 1);
}

// Scan: conf>0.9 prefilter, warp-cooperative scoring, emit s>0.9 candidates
// (key + box + fast-bin histogram + totals). Shared counter -> no reset pass.
__global__ void scan_kernel(const float* __restrict__ preds) {
    cudaTriggerProgrammaticLaunchCompletion();
    __shared__ int s_cnt;
    int b = blockIdx.y;
    int c = blockIdx.x;
    if (threadIdx.x == 0) s_cnt = 0;
    __syncthreads();
    int a0 = c * 256 + threadIdx.x;
    int lane = threadIdx.x & 31;
    bool inb = a0 < ANCH;
    float conf0 = inb ? preds[((size_t)b * ANCH + a0) * ROW + 4] : 0.0f;
    unsigned m = __ballot_sync(FULLM, inb && (conf0 > PRE_THRESH));
    unsigned long long* seg = g_cand[b] + c * SEGW;
    float4* segb = g_cbox[b] + c * SEGW;
    while (m) {
        int src = __ffs(m) - 1;
        m &= m - 1;
        int a = __shfl_sync(FULLM, a0, src);
        float conf = __shfl_sync(FULLM, conf0, src);
        const float* row = preds + ((size_t)b * ANCH + a) * ROW;
#pragma unroll
        for (int part = 0; part < 3; part++) {
            int k = part * 32 + lane;
            float p = (k < NCLS) ? row[5 + k] : 0.0f;
            float s = __fmul_rn(p, conf);
            bool pr = (k < NCLS) && (s > PRE_THRESH);
            unsigned mm = __ballot_sync(FULLM, pr);
            if (pr) {
                unsigned sb = __float_as_uint(s);
                atomicAdd(&g_hist[b][bucket_fast(sb)], 1);
                int leader = __ffs(mm) - 1;
                int rank = __popc(mm & ((1u << lane) - 1u));
                int basep;
                if (lane == leader) basep = atomicAdd(&s_cnt, __popc(mm));
                basep = __shfl_sync(mm, basep, leader);
                int pos = basep + rank;
                if (pos < SEGW) {
                    unsigned flat = (unsigned)a * 80u + (unsigned)k;
                    seg[pos] = ((unsigned long long)sb << 32) |
                               (unsigned long long)(~flat);
                    segb[pos] = make_float4(row[0], row[1], row[2], row[3]);
                }
            }
        }
    }
    __syncthreads();
    if (threadIdx.x == 0) {
        g_bcnt[b][c] = s_cnt;  // true (unsaturated) count
        atomicAdd(&g_ntot[b], s_cnt);
        if (s_cnt > SEGW) atomicOr(&g_over[b], 1);
    }
}

// Inclusive suffix sums of per-thread value v -> sm.rsum (block-wide)
__device__ __forceinline__ void suffix_scan(SMF& sm, int v, int tid,
                                            int lane, int wid) {
    int vs = v;
#pragma unroll
    for (int off = 1; off < 32; off <<= 1) {
        int t = __shfl_down_sync(FULLM, vs, off);
        if (lane + off < 32) vs += t;
    }
    if (lane == 0) sm.wred[wid] = vs;
    __syncthreads();
    if (wid == 0) {
        int w = sm.wred[lane];
        __syncwarp();
#pragma unroll
        for (int off = 1; off < 32; off <<= 1) {
            int t = __shfl_down_sync(FULLM, w, off);
            if (lane + off < 32) w += t;
        }
        sm.wred[lane] = w;  // inclusive suffix over warp totals
    }
    __syncthreads();
    sm.rsum[tid] = vs + ((wid < 31) ? sm.wred[wid + 1] : 0);
    __syncthreads();
}

__global__ void __launch_bounds__(1024, 1)
final_kernel(const float* __restrict__ preds, float* __restrict__ out) {
    extern __shared__ char smc[];
    SMF& sm = *(SMF*)smc;
    int b = blockIdx.x;
    int tid = threadIdx.x;
    int lane = tid & 31;
    int wid = tid >> 5;

    // ---- dependency-free init (overlaps scan tail via PDL) ----
    sm.skeys[tid] = 0ull;
    for (int i = tid; i < 32 * NCLS; i += 1024) sm.wcnt[i] = 0;
    sm.keepf[tid] = 0;
    if (tid == 0) { sm.cstar = NBF; sm.mcnt = 0; sm.smax = 0; }

    // ---- wait for scan_kernel's writes, then ingest its outputs ----
    cudaGridDependencySynchronize();
    {
        int v = g_hist[b][tid];   // exactly one fast bin per thread
        sm.histF[tid] = v;
        g_hist[b][tid] = 0;
        if (tid == 0) {
            sm.n_tot = g_ntot[b];
            sm.over = g_over[b];
            g_ntot[b] = 0;
            g_over[b] = 0;
        }
        __syncthreads();
        bool slow = (sm.n_tot < PRE) || sm.over;

        if (!slow) {
            // ---- fast path: suffix over 1024 bins, cutoff, bases ----
            suffix_scan(sm, v, tid, lane, wid);
            // cutoff bin: smallest bin with suffix >= PRE (rsum[0] >= PRE)
            if (sm.rsum[tid] >= PRE &&
                (tid == 1023 || sm.rsum[tid + 1] < PRE)) {
                sm.cstar = tid;
                sm.mcnt = sm.rsum[tid];
            }
            sm.bposF[tid] = (tid < 1023) ? sm.rsum[tid + 1] : 0;  // base
            __syncthreads();
            int cs = sm.cstar;

            // ---- compact: atomic cursor on bposF gives position ----
            for (int c = wid; c < ABLK; c += 32) {
                int cnt = g_bcnt[b][c];
                const unsigned long long* seg = g_cand[b] + c * SEGW;
                for (int i = lane; i < cnt; i += 32) {
                    unsigned long long key = seg[i];
                    int bk = bucket_fast((unsigned)(key >> 32));
                    if (bk >= cs) {
                        int pos = atomicAdd(&sm.bposF[bk], 1);
                        if (pos < SORTN) {
                            sm.keys[pos] = key;
                            sm.aux[pos] = c * SEGW + i;
                        }
                    }
                }
            }
            __syncthreads();

            // ---- exact rank; fill boxes from g_cbox ----
            int mC = min(sm.mcnt, SORTN);
#pragma unroll
            for (int it = 0; it < 2; it++) {
                int idx = tid + it * 1024;
                if (idx < mC) {
                    unsigned long long key = sm.keys[idx];
                    int bk = bucket_fast((unsigned)(key >> 32));
                    int endv = sm.bposF[bk];
                    int base = endv - sm.histF[bk];
                    int end = min(endv, SORTN);
                    int rank = base;
                    for (int j = base; j < end; j++)
                        rank += (sm.keys[j] > key);
                    if (rank < PRE) {
                        sm.skeys[rank] = key;
                        float4 bx = g_cbox[b][sm.aux[idx]];
                        sm.rbx1[rank] = bx.x; sm.rby1[rank] = bx.y;
                        sm.rbx2[rank] = bx.z; sm.rby2[rank] = bx.w;
                    }
                }
            }
            __syncthreads();
        } else {
            // ======= slow path (exactness-gated; statistically never) ====
#pragma unroll
            for (int q = 0; q < GRPS; q++) sm.histS[tid * GRPS + q] = 0;
            __syncthreads();
            const float* bp = preds + (size_t)b * ANCH * ROW;
            for (int i = tid; i < NSC; i += 1024) {
                int a = i / 80, k = i - a * 80;
                float s = __fmul_rn(bp[(size_t)a * ROW + 5 + k],
                                    bp[(size_t)a * ROW + 4]);
                if (s > CONF_THRESH)
                    atomicAdd(&sm.histS[bucket_slow(__float_as_uint(s))], 1);
            }
            __syncthreads();
            {
                int vs = 0;
#pragma unroll
                for (int q = 0; q < GRPS; q++) vs += sm.histS[tid * GRPS + q];
                suffix_scan(sm, vs, tid, lane, wid);
            }
            int t_target = min(PRE, sm.rsum[0]);
            if (t_target > 0 && sm.rsum[tid] >= t_target &&
                (tid == 1023 || sm.rsum[tid + 1] < t_target)) {
                int acc = (tid < 1023) ? sm.rsum[tid + 1] : 0;
                for (int bk = tid * GRPS + GRPS - 1; bk >= tid * GRPS; bk--) {
                    acc += sm.histS[bk];
                    if (acc >= t_target) {
                        sm.cstar = bk;
                        sm.mcnt = acc;
                        break;
                    }
                }
            }
            {
                int run = (tid < 1023) ? sm.rsum[tid + 1] : 0;
                for (int q = GRPS - 1; q >= 0; q--) {
                    sm.bposS[tid * GRPS + q] = run;
                    run += sm.histS[tid * GRPS + q];
                }
            }
            __syncthreads();
            int cs = sm.cstar;
            for (int i = tid; i < NSC; i += 1024) {
                int a = i / 80, k = i - a * 80;
                float s = __fmul_rn(bp[(size_t)a * ROW + 5 + k],
                                    bp[(size_t)a * ROW + 4]);
                if (s > CONF_THRESH) {
                    int bk = bucket_slow(__float_as_uint(s));
                    if (bk >= cs) {
                        int pos = atomicAdd(&sm.bposS[bk], 1);
                        if (pos < SORTN) {
                            sm.keys[pos] =
                                ((unsigned long long)__float_as_uint(s) << 32) |
                                (unsigned long long)(~(unsigned)i);
                            sm.aux[pos] = i;
                        }
                    }
                }
            }
            __syncthreads();
            int mC = min(sm.mcnt, SORTN);
#pragma unroll
            for (int it = 0; it < 2; it++) {
                int idx = tid + it * 1024;
                if (idx < mC) {
                    unsigned long long key = sm.keys[idx];
                    int bk = bucket_slow((unsigned)(key >> 32));
                    int endv = sm.bposS[bk];
                    int base = endv - sm.histS[bk];
                    int end = min(endv, SORTN);
                    int rank = base;
                    for (int j = base; j < end; j++)
                        rank += (sm.keys[j] > key);
                    if (rank < PRE) {
                        sm.skeys[rank] = key;
                        unsigned flat = (unsigned)sm.aux[idx];
                        const float* row = bp + (size_t)(flat / 80u) * ROW;
                        sm.rbx1[rank] = row[0]; sm.rby1[rank] = row[1];
                        sm.rbx2[rank] = row[2]; sm.rby2[rank] = row[3];
                    }
                }
            }
            __syncthreads();
        }
    }

    // ---- decode top-1000: score/label; block max via warp reduce ----
    {
        unsigned long long key = (tid < PRE) ? sm.skeys[tid] : 0ull;
        float sc = -1.0f;
        unsigned flat = 0u;
        if (tid < PRE && key != 0ull) {
            sc = __uint_as_float((unsigned)(key >> 32));
            flat = ~((unsigned)(key & 0xffffffffull));
        }
        unsigned lbl = flat - (flat / 80u) * 80u;
        sm.ssc[tid] = sc;
        sm.slb[tid] = (int)lbl;
        int mxb = 0;  // coords >= 0 so int-bit order = float order
        if (tid < PRE && key != 0ull) {
            float mx = fmaxf(fmaxf(sm.rbx1[tid], sm.rby1[tid]),
                             fmaxf(sm.rbx2[tid], sm.rby2[tid]));
            mxb = __float_as_int(mx);
        }
#pragma unroll
        for (int off = 16; off > 0; off >>= 1)
            mxb = max(mxb, __shfl_xor_sync(FULLM, mxb, off));
        if (lane == 0) atomicMax(&sm.smax, mxb);
    }
    __syncthreads();

    // ---- class shift (bit-exact reference arithmetic) ----
    {
        float M = __int_as_float(sm.smax);
        float shb = __fadd_rn(M, 1.0f);
        float sh = __fmul_rn((float)sm.slb[tid], shb);
        float x1 = __fadd_rn(sm.rbx1[tid], sh);
        float y1 = __fadd_rn(sm.rby1[tid], sh);
        float x2 = __fadd_rn(sm.rbx2[tid], sh);
        float y2 = __fadd_rn(sm.rby2[tid], sh);
        sm.sx1[tid] = x1; sm.sy1[tid] = y1; sm.sx2[tid] = x2; sm.sy2[tid] = y2;
        sm.sar[tid] = __fmul_rn(fmaxf(__fsub_rn(x2, x1), 0.0f),
                                fmaxf(__fsub_rn(y2, y1), 0.0f));
    }

    // ---- stable per-class grouping: match_any + cross-warp shfl scan ----
    int mylbl = (tid < PRE) ? sm.slb[tid] : -1;
    unsigned grpm = __match_any_sync(FULLM, mylbl);
    int wrank = __popc(grpm & ((1u << lane) - 1u));
    if (tid < PRE && wrank == 0)
        sm.wcnt[wid * NCLS + mylbl] = __popc(grpm);
    __syncthreads();
    for (int c = wid; c < NCLS; c += 32) {
        int v = sm.wcnt[lane * NCLS + c];
        int x = v;
#pragma unroll
        for (int off = 1; off < 32; off <<= 1) {
            int t = __shfl_up_sync(FULLM, x, off);
            if (lane >= off) x += t;
        }
        sm.wof[lane * NCLS + c] = x - v;  // exclusive
        if (lane == 31) sm.ccnt[c] = x;
    }
    __syncthreads();
    if (tid < PRE) {
        int pos = sm.wof[wid * NCLS + mylbl] + wrank;
        if (pos < MAXK) sm.clist[mylbl * MAXK + pos] = tid;
    }
    __syncthreads();

    // ---- warp-parallel per-class greedy NMS (one warp per class) ----
    for (int c = wid; c < NCLS; c += 32) {
        int kc = min(sm.ccnt[c], MAXK);
        if (kc == 0) continue;
        if (kc <= 32) {
            int j1 = (lane < kc) ? sm.clist[c * MAXK + lane] : 0;
            float x1a = sm.sx1[j1], y1a = sm.sy1[j1];
            float x2a = sm.sx2[j1], y2a = sm.sy2[j1], ara = sm.sar[j1];
            unsigned keep =
                __ballot_sync(FULLM, lane < kc && sm.ssc[j1] > CONF_THRESH);
            for (int ii = 0; ii < kc; ii++) {
                if (!((keep >> ii) & 1u)) continue;  // warp-uniform
                float px1 = __shfl_sync(FULLM, x1a, ii);
                float py1 = __shfl_sync(FULLM, y1a, ii);
                float px2 = __shfl_sync(FULLM, x2a, ii);
                float py2 = __shfl_sync(FULLM, y2a, ii);
                float par = __shfl_sync(FULLM, ara, ii);
                float iw = fmaxf(__fsub_rn(fminf(px2, x2a), fmaxf(px1, x1a)), 0.0f);
                float ih = fmaxf(__fsub_rn(fminf(py2, y2a), fmaxf(py1, y1a)), 0.0f);
                float inter = __fmul_rn(iw, ih);
                float den = __fadd_rn(__fsub_rn(__fadd_rn(par, ara), inter), 1e-7f);
                bool s1 = (lane > ii) && (lane < kc) &&
                          (__fdiv_rn(inter, den) > NMS_THRESH);
                keep &= ~__ballot_sync(FULLM, s1);
            }
            if (lane < kc) sm.keepf[j1] = (int)((keep >> lane) & 1u);
        } else {
            int i1 = lane, i2 = lane + 32;
            int j1 = sm.clist[c * MAXK + i1];
            int j2 = (i2 < kc) ? sm.clist[c * MAXK + i2] : 0;
            float x1a = sm.sx1[j1], y1a = sm.sy1[j1];
            float x2a = sm.sx2[j1], y2a = sm.sy2[j1], ara = sm.sar[j1];
            float x1b = sm.sx1[j2], y1b = sm.sy1[j2];
            float x2b = sm.sx2[j2], y2b = sm.sy2[j2], arb = sm.sar[j2];
            unsigned m1 = __ballot_sync(FULLM, sm.ssc[j1] > CONF_THRESH);
            unsigned m2 =
                __ballot_sync(FULLM, i2 < kc && sm.ssc[j2] > CONF_THRESH);
            unsigned long long keep =
                (unsigned long long)m1 | ((unsigned long long)m2 << 32);
            for (int ii = 0; ii < kc; ii++) {
                if (!((keep >> ii) & 1ull)) continue;
                int src = ii & 31;
                bool hi = ii >= 32;
                float px1 = __shfl_sync(FULLM, hi ? x1b : x1a, src);
                float py1 = __shfl_sync(FULLM, hi ? y1b : y1a, src);
                float px2 = __shfl_sync(FULLM, hi ? x2b : x2a, src);
                float py2 = __shfl_sync(FULLM, hi ? y2b : y2a, src);
                float par = __shfl_sync(FULLM, hi ? arb : ara, src);
                float iw1 = fmaxf(__fsub_rn(fminf(px2, x2a), fmaxf(px1, x1a)), 0.0f);
                float ih1 = fmaxf(__fsub_rn(fminf(py2, y2a), fmaxf(py1, y1a)), 0.0f);
                float it1 = __fmul_rn(iw1, ih1);
                float dn1 = __fadd_rn(__fsub_rn(__fadd_rn(par, ara), it1), 1e-7f);
                bool s1 = (i1 > ii) && (__fdiv_rn(it1, dn1) > NMS_THRESH);
                float iw2 = fmaxf(__fsub_rn(fminf(px2, x2b), fmaxf(px1, x1b)), 0.0f);
                float ih2 = fmaxf(__fsub_rn(fminf(py2, y2b), fmaxf(py1, y1b)), 0.0f);
                float it2 = __fmul_rn(iw2, ih2);
                float dn2 = __fadd_rn(__fsub_rn(__fadd_rn(par, arb), it2), 1e-7f);
                bool s2 = (i2 > ii) && (i2 < kc) &&
                          (__fdiv_rn(it2, dn2) > NMS_THRESH);
                unsigned b1 = __ballot_sync(FULLM, s1);
                unsigned b2 = __ballot_sync(FULLM, s2);
                keep &= ~((unsigned long long)b1 |
                          ((unsigned long long)b2 << 32));
            }
            sm.keepf[j1] = (int)((keep >> i1) & 1ull);
            if (i2 < kc) sm.keepf[j2] = (int)((keep >> i2) & 1ull);
        }
    }
    __syncthreads();

    // ---- keep-flag prefix sum (warp shuffles) ----
    int myscan, total;
    {
        int p = sm.keepf[tid];
#pragma unroll
        for (int off = 1; off < 32; off <<= 1) {
            int t = __shfl_up_sync(FULLM, p, off);
            if (lane >= off) p += t;
        }
        if (lane == 31) sm.wscan[wid] = p;
        __syncthreads();
        if (wid == 0) {
            int w = sm.wscan[lane];
            __syncwarp();
#pragma unroll
            for (int off = 1; off < 32; off <<= 1) {
                int t = __shfl_up_sync(FULLM, w, off);
                if (lane >= off) w += t;
            }
            sm.wscan[lane] = w;
        }
        __syncthreads();
        int base = (wid > 0) ? sm.wscan[wid - 1] : 0;
        myscan = base + p;
        total = sm.wscan[31];
    }

    // ---- emit top-300 ----
    float* ob = out;                               // [16][300][4]
    float* os = out + (size_t)BATCH * MAXDET * 4;  // [16][300]
    float* ol = out + (size_t)BATCH * MAXDET * 5;  // [16][300] labels as f32

    if (tid < PRE && sm.keepf[tid]) {
        int m = myscan - 1;
        if (m < MAXDET) {
            float* p = ob + ((size_t)b * MAXDET + m) * 4;
            p[0] = sm.rbx1[tid]; p[1] = sm.rby1[tid];
            p[2] = sm.rbx2[tid]; p[3] = sm.rby2[tid];
            os[b * MAXDET + m] = sm.ssc[tid];
            ol[b * MAXDET + m] = (float)sm.slb[tid];
        }
    }
    for (int m = tid; m < MAXDET; m += 1024) {
        if (m >= total) {
            float* p = ob + ((size_t)b * MAXDET + m) * 4;
            p[0] = 0.0f; p[1] = 0.0f; p[2] = 0.0f; p[3] = 0.0f;
            os[b * MAXDET + m] = 0.0f;
            ol[b * MAXDET + m] = -1.0f;
        }
    }
}

extern "C" void kernel_launch(void* const* d_in, const int* in_sizes, int n_in,
                              void* d_out, int out_size) {
    (void)in_sizes; (void)n_in; (void)out_size;
    const float* preds = (const float*)d_in[0];
    float* out = (float*)d_out;

    cudaFuncSetAttribute(final_kernel,
                         cudaFuncAttributeMaxDynamicSharedMemorySize,
                         (int)sizeof(SMF));

    scan_kernel<<<dim3(ABLK, BATCH), 256>>>(preds);

    cudaLaunchConfig_t cfg = {};
    cfg.gridDim = dim3(BATCH, 1, 1);
    cfg.blockDim = dim3(1024, 1, 1);
    cfg.dynamicSmemBytes = sizeof(SMF);
    cfg.stream = 0;
    cudaLaunchAttribute at[1];
    at[0].id = cudaLaunchAttributeProgrammaticStreamSerialization;
    at[0].val.programmaticStreamSerializationAllowed = 1;
    cfg.attrs = at;
    cfg.numAttrs = 1;
    cudaLaunchKernelEx(&cfg, final_kernel, preds, out);
}

// round 13
// speedup vs baseline: 1.3677x; 1.0307x over previous
#include <cuda_runtime.h>

#define BATCH 16
#define ANCH 22743
#define ROW 85
#define NCLS 80
#define NSC (ANCH * NCLS)
#define ABLK 89            // ceil(ANCH / 256)
#define SEGW 1024          // candidate slots per scan block
#define PRE 1000
#define MAXDET 300
#define CONF_THRESH 0.2f
#define PRE_THRESH 0.9f
#define HI_THRESH 0.96f    // bits 0x3F75C28F
#define NMS_THRESH 0.45f
#define MAXK 64
#define SORTN 2048
#define FULLM 0xffffffffu

// fast-path bins over (0.9, 1.0): (bits - bits(0.9f)) >> 11, 1024 bins
#define B9OFF 0x3F666666u
#define NBF 1024
#define HBIN 492           // bin >= HBIN  =>  bits >= 0x3F75C666 > bits(0.96f)
#define HCAP 4096          // high-list capacity (mean ~1475, 68 sigma)
// slow-path histogram over (0.2, 1.0): (bits - 0x3E000000) >> 12
#define NBS 6144
#define B2OFF 0x3E000000u
#define GRPS 6             // NBS / 1024

// ---------------- device scratch (static; no allocations) ----------------
__device__ unsigned long long g_cand[BATCH][ABLK * SEGW];
__device__ float4 g_cbox[BATCH][ABLK * SEGW];
__device__ int g_bcnt[BATCH][ABLK];
__device__ unsigned long long g_hkey[BATCH][HCAP];   // dense s>0.96 tier
__device__ float4 g_hbox[BATCH][HCAP];
__device__ int g_hcnt[BATCH];
__device__ int g_hist[BATCH][NBF];   // zero at load; final re-zeroes each run
__device__ int g_ntot[BATCH];
__device__ int g_over[BATCH];

struct SMF {
    unsigned long long keys[SORTN];   // bucket-grouped candidates >= cutoff
    unsigned long long skeys[1024];   // rank-ordered top-1000 keys
    int aux[SORTN];                   // hi-slot (fast) / seg-slot (med) / flat
    int histF[NBF];                   // fast bin counts (1 per thread)
    int bposF[NBF];                   // fast bin base, then scatter cursor
    int histS[NBS];                   // slow-path histogram
    int bposS[NBS];
    int rsum[1024];                   // suffix sums (shared fast/slow)
    int wred[33];
    int wcnt[32 * NCLS];
    int wof[32 * NCLS];
    int ccnt[NCLS];
    float rbx1[1024], rby1[1024], rbx2[1024], rby2[1024];
    float sx1[1024], sy1[1024], sx2[1024], sy2[1024], sar[1024];
    float ssc[1024];
    int slb[1024];
    int clist[NCLS * MAXK];
    int keepf[1024];
    int wscan[33];
    int n_tot, over, n_high, cstar, mcnt, smax;
};

__device__ __forceinline__ int bucket_fast(unsigned sb) {
    return min((int)((sb - B9OFF) >> 11), NBF - 1);
}
__device__ __forceinline__ int bucket_slow(unsigned sb) {
    return min((int)((sb - B2OFF) >> 12), NBS - 1);
}

// Scan: conf>0.9 prefilter, warp-cooperative scoring, emit s>0.9 candidates
// (key + box + fast-bin histogram + totals), plus dense s>0.96 high tier.
__global__ void scan_kernel(const float* __restrict__ preds) {
    cudaTriggerProgrammaticLaunchCompletion();
    __shared__ int s_cnt;
    int b = blockIdx.y;
    int c = blockIdx.x;
    if (threadIdx.x == 0) s_cnt = 0;
    __syncthreads();
    int a0 = c * 256 + threadIdx.x;
    int lane = threadIdx.x & 31;
    bool inb = a0 < ANCH;
    float conf0 = inb ? preds[((size_t)b * ANCH + a0) * ROW + 4] : 0.0f;
    unsigned m = __ballot_sync(FULLM, inb && (conf0 > PRE_THRESH));
    unsigned long long* seg = g_cand[b] + c * SEGW;
    float4* segb = g_cbox[b] + c * SEGW;
    while (m) {
        int src = __ffs(m) - 1;
        m &= m - 1;
        int a = __shfl_sync(FULLM, a0, src);
        float conf = __shfl_sync(FULLM, conf0, src);
        const float* row = preds + ((size_t)b * ANCH + a) * ROW;
        float b0 = row[0], b1 = row[1], b2 = row[2], b3 = row[3];
#pragma unroll
        for (int part = 0; part < 3; part++) {
            int k = part * 32 + lane;
            float p = (k < NCLS) ? row[5 + k] : 0.0f;
            float s = __fmul_rn(p, conf);
            bool pr = (k < NCLS) && (s > PRE_THRESH);
            unsigned mm = __ballot_sync(FULLM, pr);
            if (pr) {
                unsigned sb = __float_as_uint(s);
                atomicAdd(&g_hist[b][bucket_fast(sb)], 1);
                unsigned flat = (unsigned)a * 80u + (unsigned)k;
                unsigned long long key =
                    ((unsigned long long)sb << 32) |
                    (unsigned long long)(~flat);
                if (s > HI_THRESH) {
                    int hp = atomicAdd(&g_hcnt[b], 1);
                    if (hp < HCAP) {
                        g_hkey[b][hp] = key;
                        g_hbox[b][hp] = make_float4(b0, b1, b2, b3);
                    }
                }
                int leader = __ffs(mm) - 1;
                int rank = __popc(mm & ((1u << lane) - 1u));
                int basep;
                if (lane == leader) basep = atomicAdd(&s_cnt, __popc(mm));
                basep = __shfl_sync(mm, basep, leader);
                int pos = basep + rank;
                if (pos < SEGW) {
                    seg[pos] = key;
                    segb[pos] = make_float4(b0, b1, b2, b3);
                }
            }
        }
    }
    __syncthreads();
    if (threadIdx.x == 0) {
        g_bcnt[b][c] = s_cnt;  // true (unsaturated) count
        atomicAdd(&g_ntot[b], s_cnt);
        if (s_cnt > SEGW) atomicOr(&g_over[b], 1);
    }
}

// Inclusive suffix sums of per-thread value v -> sm.rsum (block-wide)
__device__ __forceinline__ void suffix_scan(SMF& sm, int v, int tid,
                                            int lane, int wid) {
    int vs = v;
#pragma unroll
    for (int off = 1; off < 32; off <<= 1) {
        int t = __shfl_down_sync(FULLM, vs, off);
        if (lane + off < 32) vs += t;
    }
    if (lane == 0) sm.wred[wid] = vs;
    __syncthreads();
    if (wid == 0) {
        int w = sm.wred[lane];
        __syncwarp();
#pragma unroll
        for (int off = 1; off < 32; off <<= 1) {
            int t = __shfl_down_sync(FULLM, w, off);
            if (lane + off < 32) w += t;
        }
        sm.wred[lane] = w;  // inclusive suffix over warp totals
    }
    __syncthreads();
    sm.rsum[tid] = vs + ((wid < 31) ? sm.wred[wid + 1] : 0);
    __syncthreads();
}

__global__ void __launch_bounds__(1024, 1)
final_kernel(const float* __restrict__ preds, float* __restrict__ out) {
    extern __shared__ char smc[];
    SMF& sm = *(SMF*)smc;
    int b = blockIdx.x;
    int tid = threadIdx.x;
    int lane = tid & 31;
    int wid = tid >> 5;

    // ---- dependency-free init ----
    sm.skeys[tid] = 0ull;
    for (int i = tid; i < 32 * NCLS; i += 1024) sm.wcnt[i] = 0;
    sm.keepf[tid] = 0;
    if (tid == 0) { sm.cstar = NBF; sm.mcnt = 0; sm.smax = 0; }

    // ---- wait for scan_kernel's writes, then ingest its outputs ----
    cudaGridDependencySynchronize();
    {
        int v = g_hist[b][tid];   // exactly one fast bin per thread
        sm.histF[tid] = v;
        g_hist[b][tid] = 0;
        if (tid == 0) {
            sm.n_tot = g_ntot[b];
            sm.over = g_over[b];
            sm.n_high = g_hcnt[b];
            g_ntot[b] = 0;
            g_over[b] = 0;
            g_hcnt[b] = 0;
        }
        __syncthreads();
        bool slow = (sm.n_tot < PRE) || sm.over;

        if (!slow) {
            // ---- fast path: suffix over 1024 bins, cutoff, bases ----
            suffix_scan(sm, v, tid, lane, wid);
            if (sm.rsum[tid] >= PRE &&
                (tid == 1023 || sm.rsum[tid + 1] < PRE)) {
                sm.cstar = tid;
                sm.mcnt = sm.rsum[tid];
            }
            sm.bposF[tid] = (tid < 1023) ? sm.rsum[tid + 1] : 0;  // base
            __syncthreads();
            int cs = sm.cstar;
            bool hi_ok = (cs >= HBIN) && (sm.n_high <= HCAP);

            // ---- compact: dense high tier (usual) or segments (rare) ----
            if (hi_ok) {
                int nh = sm.n_high;
                for (int i = tid; i < nh; i += 1024) {
                    unsigned long long key = g_hkey[b][i];
                    int bk = bucket_fast((unsigned)(key >> 32));
                    if (bk >= cs) {
                        int pos = atomicAdd(&sm.bposF[bk], 1);
                        if (pos < SORTN) {
                            sm.keys[pos] = key;
                            sm.aux[pos] = i;
                        }
                    }
                }
            } else {
                for (int c = wid; c < ABLK; c += 32) {
                    int cnt = g_bcnt[b][c];
                    const unsigned long long* seg = g_cand[b] + c * SEGW;
                    for (int i = lane; i < cnt; i += 32) {
                        unsigned long long key = seg[i];
                        int bk = bucket_fast((unsigned)(key >> 32));
                        if (bk >= cs) {
                            int pos = atomicAdd(&sm.bposF[bk], 1);
                            if (pos < SORTN) {
                                sm.keys[pos] = key;
                                sm.aux[pos] = c * SEGW + i;
                            }
                        }
                    }
                }
            }
            __syncthreads();

            // ---- exact rank; fill boxes ----
            int mC = min(sm.mcnt, SORTN);
#pragma unroll
            for (int it = 0; it < 2; it++) {
                int idx = tid + it * 1024;
                if (idx < mC) {
                    unsigned long long key = sm.keys[idx];
                    int bk = bucket_fast((unsigned)(key >> 32));
                    int endv = sm.bposF[bk];
                    int base = endv - sm.histF[bk];
                    int end = min(endv, SORTN);
                    int rank = base;
                    for (int j = base; j < end; j++)
                        rank += (sm.keys[j] > key);
                    if (rank < PRE) {
                        sm.skeys[rank] = key;
                        float4 bx = hi_ok ? g_hbox[b][sm.aux[idx]]
                                          : g_cbox[b][sm.aux[idx]];
                        sm.rbx1[rank] = bx.x; sm.rby1[rank] = bx.y;
                        sm.rbx2[rank] = bx.z; sm.rby2[rank] = bx.w;
                    }
                }
            }
            __syncthreads();
        } else {
            // ======= slow path (exactness-gated; statistically never) ====
#pragma unroll
            for (int q = 0; q < GRPS; q++) sm.histS[tid * GRPS + q] = 0;
            __syncthreads();
            const float* bp = preds + (size_t)b * ANCH * ROW;
            for (int i = tid; i < NSC; i += 1024) {
                int a = i / 80, k = i - a * 80;
                float s = __fmul_rn(bp[(size_t)a * ROW + 5 + k],
                                    bp[(size_t)a * ROW + 4]);
                if (s > CONF_THRESH)
                    atomicAdd(&sm.histS[bucket_slow(__float_as_uint(s))], 1);
            }
            __syncthreads();
            {
                int vs = 0;
#pragma unroll
                for (int q = 0; q < GRPS; q++) vs += sm.histS[tid * GRPS + q];
                suffix_scan(sm, vs, tid, lane, wid);
            }
            int t_target = min(PRE, sm.rsum[0]);
            if (t_target > 0 && sm.rsum[tid] >= t_target &&
                (tid == 1023 || sm.rsum[tid + 1] < t_target)) {
                int acc = (tid < 1023) ? sm.rsum[tid + 1] : 0;
                for (int bk = tid * GRPS + GRPS - 1; bk >= tid * GRPS; bk--) {
                    acc += sm.histS[bk];
                    if (acc >= t_target) {
                        sm.cstar = bk;
                        sm.mcnt = acc;
                        break;
                    }
                }
            }
            {
                int run = (tid < 1023) ? sm.rsum[tid + 1] : 0;
                for (int q = GRPS - 1; q >= 0; q--) {
                    sm.bposS[tid * GRPS + q] = run;
                    run += sm.histS[tid * GRPS + q];
                }
            }
            __syncthreads();
            int cs = sm.cstar;
            for (int i = tid; i < NSC; i += 1024) {
                int a = i / 80, k = i - a * 80;
                float s = __fmul_rn(bp[(size_t)a * ROW + 5 + k],
                                    bp[(size_t)a * ROW + 4]);
                if (s > CONF_THRESH) {
                    int bk = bucket_slow(__float_as_uint(s));
                    if (bk >= cs) {
                        int pos = atomicAdd(&sm.bposS[bk], 1);
                        if (pos < SORTN) {
                            sm.keys[pos] =
                                ((unsigned long long)__float_as_uint(s) << 32) |
                                (unsigned long long)(~(unsigned)i);
                            sm.aux[pos] = i;
                        }
                    }
                }
            }
            __syncthreads();
            int mC = min(sm.mcnt, SORTN);
#pragma unroll
            for (int it = 0; it < 2; it++) {
                int idx = tid + it * 1024;
                if (idx < mC) {
                    unsigned long long key = sm.keys[idx];
                    int bk = bucket_slow((unsigned)(key >> 32));
                    int endv = sm.bposS[bk];
                    int base = endv - sm.histS[bk];
                    int end = min(endv, SORTN);
                    int rank = base;
                    for (int j = base; j < end; j++)
                        rank += (sm.keys[j] > key);
                    if (rank < PRE) {
                        sm.skeys[rank] = key;
                        unsigned flat = (unsigned)sm.aux[idx];
                        const float* row = bp + (size_t)(flat / 80u) * ROW;
                        sm.rbx1[rank] = row[0]; sm.rby1[rank] = row[1];
                        sm.rbx2[rank] = row[2]; sm.rby2[rank] = row[3];
                    }
                }
            }
            __syncthreads();
        }
    }

    // ---- decode top-1000: score/label; block max via warp reduce ----
    {
        unsigned long long key = (tid < PRE) ? sm.skeys[tid] : 0ull;
        float sc = -1.0f;
        unsigned flat = 0u;
        if (tid < PRE && key != 0ull) {
            sc = __uint_as_float((unsigned)(key >> 32));
            flat = ~((unsigned)(key & 0xffffffffull));
        }
        unsigned lbl = flat - (flat / 80u) * 80u;
        sm.ssc[tid] = sc;
        sm.slb[tid] = (int)lbl;
        int mxb = 0;  // coords >= 0 so int-bit order = float order
        if (tid < PRE && key != 0ull) {
            float mx = fmaxf(fmaxf(sm.rbx1[tid], sm.rby1[tid]),
                             fmaxf(sm.rbx2[tid], sm.rby2[tid]));
            mxb = __float_as_int(mx);
        }
#pragma unroll
        for (int off = 16; off > 0; off >>= 1)
            mxb = max(mxb, __shfl_xor_sync(FULLM, mxb, off));
        if (lane == 0) atomicMax(&sm.smax, mxb);
    }
    __syncthreads();

    // ---- class shift (bit-exact reference arithmetic) ----
    {
        float M = __int_as_float(sm.smax);
        float shb = __fadd_rn(M, 1.0f);
        float sh = __fmul_rn((float)sm.slb[tid], shb);
        float x1 = __fadd_rn(sm.rbx1[tid], sh);
        float y1 = __fadd_rn(sm.rby1[tid], sh);
        float x2 = __fadd_rn(sm.rbx2[tid], sh);
        float y2 = __fadd_rn(sm.rby2[tid], sh);
        sm.sx1[tid] = x1; sm.sy1[tid] = y1; sm.sx2[tid] = x2; sm.sy2[tid] = y2;
        sm.sar[tid] = __fmul_rn(fmaxf(__fsub_rn(x2, x1), 0.0f),
                                fmaxf(__fsub_rn(y2, y1), 0.0f));
    }

    // ---- stable per-class grouping: match_any + cross-warp shfl scan ----
    int mylbl = (tid < PRE) ? sm.slb[tid] : -1;
    unsigned grpm = __match_any_sync(FULLM, mylbl);
    int wrank = __popc(grpm & ((1u << lane) - 1u));
    if (tid < PRE && wrank == 0)
        sm.wcnt[wid * NCLS + mylbl] = __popc(grpm);
    __syncthreads();
    for (int c = wid; c < NCLS; c += 32) {
        int v = sm.wcnt[lane * NCLS + c];
        int x = v;
#pragma unroll
        for (int off = 1; off < 32; off <<= 1) {
            int t = __shfl_up_sync(FULLM, x, off);
            if (lane >= off) x += t;
        }
        sm.wof[lane * NCLS + c] = x - v;  // exclusive
        if (lane == 31) sm.ccnt[c] = x;
    }
    __syncthreads();
    if (tid < PRE) {
        int pos = sm.wof[wid * NCLS + mylbl] + wrank;
        if (pos < MAXK) sm.clist[mylbl * MAXK + pos] = tid;
    }
    __syncthreads();

    // ---- warp-parallel per-class greedy NMS (one warp per class) ----
    for (int c = wid; c < NCLS; c += 32) {
        int kc = min(sm.ccnt[c], MAXK);
        if (kc == 0) continue;
        if (kc <= 32) {
            int j1 = (lane < kc) ? sm.clist[c * MAXK + lane] : 0;
            float x1a = sm.sx1[j1], y1a = sm.sy1[j1];
            float x2a = sm.sx2[j1], y2a = sm.sy2[j1], ara = sm.sar[j1];
            unsigned keep =
                __ballot_sync(FULLM, lane < kc && sm.ssc[j1] > CONF_THRESH);
            for (int ii = 0; ii < kc; ii++) {
                if (!((keep >> ii) & 1u)) continue;  // warp-uniform
                float px1 = __shfl_sync(FULLM, x1a, ii);
                float py1 = __shfl_sync(FULLM, y1a, ii);
                float px2 = __shfl_sync(FULLM, x2a, ii);
                float py2 = __shfl_sync(FULLM, y2a, ii);
                float par = __shfl_sync(FULLM, ara, ii);
                float iw = fmaxf(__fsub_rn(fminf(px2, x2a), fmaxf(px1, x1a)), 0.0f);
                float ih = fmaxf(__fsub_rn(fminf(py2, y2a), fmaxf(py1, y1a)), 0.0f);
                float inter = __fmul_rn(iw, ih);
                float den = __fadd_rn(__fsub_rn(__fadd_rn(par, ara), inter), 1e-7f);
                bool s1 = (lane > ii) && (lane < kc) &&
                          (__fdiv_rn(inter, den) > NMS_THRESH);
                keep &= ~__ballot_sync(FULLM, s1);
            }
            if (lane < kc) sm.keepf[j1] = (int)((keep >> lane) & 1u);
        } else {
            int i1 = lane, i2 = lane + 32;
            int j1 = sm.clist[c * MAXK + i1];
            int j2 = (i2 < kc) ? sm.clist[c * MAXK + i2] : 0;
            float x1a = sm.sx1[j1], y1a = sm.sy1[j1];
            float x2a = sm.sx2[j1], y2a = sm.sy2[j1], ara = sm.sar[j1];
            float x1b = sm.sx1[j2], y1b = sm.sy1[j2];
            float x2b = sm.sx2[j2], y2b = sm.sy2[j2], arb = sm.sar[j2];
            unsigned m1 = __ballot_sync(FULLM, sm.ssc[j1] > CONF_THRESH);
            unsigned m2 =
                __ballot_sync(FULLM, i2 < kc && sm.ssc[j2] > CONF_THRESH);
            unsigned long long keep =
                (unsigned long long)m1 | ((unsigned long long)m2 << 32);
            for (int ii = 0; ii < kc; ii++) {
                if (!((keep >> ii) & 1ull)) continue;
                int src = ii & 31;
                bool hi = ii >= 32;
                float px1 = __shfl_sync(FULLM, hi ? x1b : x1a, src);
                float py1 = __shfl_sync(FULLM, hi ? y1b : y1a, src);
                float px2 = __shfl_sync(FULLM, hi ? x2b : x2a, src);
                float py2 = __shfl_sync(FULLM, hi ? y2b : y2a, src);
                float par = __shfl_sync(FULLM, hi ? arb : ara, src);
                float iw1 = fmaxf(__fsub_rn(fminf(px2, x2a), fmaxf(px1, x1a)), 0.0f);
                float ih1 = fmaxf(__fsub_rn(fminf(py2, y2a), fmaxf(py1, y1a)), 0.0f);
                float it1 = __fmul_rn(iw1, ih1);
                float dn1 = __fadd_rn(__fsub_rn(__fadd_rn(par, ara), it1), 1e-7f);
                bool s1 = (i1 > ii) && (__fdiv_rn(it1, dn1) > NMS_THRESH);
                float iw2 = fmaxf(__fsub_rn(fminf(px2, x2b), fmaxf(px1, x1b)), 0.0f);
                float ih2 = fmaxf(__fsub_rn(fminf(py2, y2b), fmaxf(py1, y1b)), 0.0f);
                float it2 = __fmul_rn(iw2, ih2);
                float dn2 = __fadd_rn(__fsub_rn(__fadd_rn(par, arb), it2), 1e-7f);
                bool s2 = (i2 > ii) && (i2 < kc) &&
                          (__fdiv_rn(it2, dn2) > NMS_THRESH);
                unsigned b1 = __ballot_sync(FULLM, s1);
                unsigned b2 = __ballot_sync(FULLM, s2);
                keep &= ~((unsigned long long)b1 |
                          ((unsigned long long)b2 << 32));
            }
            sm.keepf[j1] = (int)((keep >> i1) & 1ull);
            if (i2 < kc) sm.keepf[j2] = (int)((keep >> i2) & 1ull);
        }
    }
    __syncthreads();

    // ---- keep-flag prefix sum (warp shuffles) ----
    int myscan, total;
    {
        int p = sm.keepf[tid];
#pragma unroll
        for (int off = 1; off < 32; off <<= 1) {
            int t = __shfl_up_sync(FULLM, p, off);
            if (lane >= off) p += t;
        }
        if (lane == 31) sm.wscan[wid] = p;
        __syncthreads();
        if (wid == 0) {
            int w = sm.wscan[lane];
            __syncwarp();
#pragma unroll
            for (int off = 1; off < 32; off <<= 1) {
                int t = __shfl_up_sync(FULLM, w, off);
                if (lane >= off) w += t;
            }
            sm.wscan[lane] = w;
        }
        __syncthreads();
        int base = (wid > 0) ? sm.wscan[wid - 1] : 0;
        myscan = base + p;
        total = sm.wscan[31];
    }

    // ---- emit top-300 ----
    float* ob = out;                               // [16][300][4]
    float* os = out + (size_t)BATCH * MAXDET * 4;  // [16][300]
    float* ol = out + (size_t)BATCH * MAXDET * 5;  // [16][300] labels as f32

    if (tid < PRE && sm.keepf[tid]) {
        int m = myscan - 1;
        if (m < MAXDET) {
            float* p = ob + ((size_t)b * MAXDET + m) * 4;
            p[0] = sm.rbx1[tid]; p[1] = sm.rby1[tid];
            p[2] = sm.rbx2[tid]; p[3] = sm.rby2[tid];
            os[b * MAXDET + m] = sm.ssc[tid];
            ol[b * MAXDET + m] = (float)sm.slb[tid];
        }
    }
    for (int m = tid; m < MAXDET; m += 1024) {
        if (m >= total) {
            float* p = ob + ((size_t)b * MAXDET + m) * 4;
            p[0] = 0.0f; p[1] = 0.0f; p[2] = 0.0f; p[3] = 0.0f;
            os[b * MAXDET + m] = 0.0f;
            ol[b * MAXDET + m] = -1.0f;
        }
    }
}

extern "C" void kernel_launch(void* const* d_in, const int* in_sizes, int n_in,
                              void* d_out, int out_size) {
    (void)in_sizes; (void)n_in; (void)out_size;
    const float* preds = (const float*)d_in[0];
    float* out = (float*)d_out;

    cudaFuncSetAttribute(final_kernel,
                         cudaFuncAttributeMaxDynamicSharedMemorySize,
                         (int)sizeof(SMF));

    scan_kernel<<<dim3(ABLK, BATCH), 256>>>(preds);

    cudaLaunchConfig_t cfg = {};
    cfg.gridDim = dim3(BATCH, 1, 1);
    cfg.blockDim = dim3(1024, 1, 1);
    cfg.dynamicSmemBytes = sizeof(SMF);
    cfg.stream = 0;
    cudaLaunchAttribute at[1];
    at[0].id = cudaLaunchAttributeProgrammaticStreamSerialization;
    at[0].val.programmaticStreamSerializationAllowed = 1;
    cfg.attrs = at;
    cfg.numAttrs = 1;
    cudaLaunchKernelEx(&cfg, final_kernel, preds, out);
}

// round 14
// speedup vs baseline: 1.4358x; 1.0498x over previous
#include <cuda_runtime.h>

#define BATCH 16
#define ANCH 22743
#define ROW 85
#define NCLS 80
#define NSC (ANCH * NCLS)
#define ABLK 89            // ceil(ANCH / 256)
#define PRE 1000
#define MAXDET 300
#define CONF_THRESH 0.2f
#define PRE_THRESH 0.9f
#define HI_THRESH 0.96f    // bits 0x3F75C28F
#define NMS_THRESH 0.45f
#define MAXK 64
#define SORTN 2048
#define FULLM 0xffffffffu

// fast-path bins over (0.9, 1.0): (bits - bits(0.9f)) >> 11, 1024 bins
#define B9OFF 0x3F666666u
#define NBF 1024
#define HBIN 492           // bin >= HBIN  =>  bits >= 0x3F75C666 > bits(0.96f)
#define HCAP 4096          // high-list capacity (mean ~1475, ~68 sigma)
// slow-path histogram over (0.2, 1.0): (bits - 0x3E000000) >> 12
#define NBS 6144
#define B2OFF 0x3E000000u
#define GRPS 6             // NBS / 1024

// ---------------- device scratch (static; no allocations) ----------------
__device__ unsigned long long g_hkey[BATCH][HCAP];   // dense s>0.96 tier
__device__ float4 g_hbox[BATCH][HCAP];
__device__ int g_hcnt[BATCH];
__device__ int g_hist[BATCH][NBF];   // zero at load; final re-zeroes each run

struct SMF {
    unsigned long long keys[SORTN];   // bin-grouped candidates >= cutoff
    int aux[SORTN];                   // high-list slot (fast) / flat (slow)
    int histF[NBF];                   // fast bin counts (1 per thread)
    int bposF[NBF];                   // fast bin base, then scatter cursor
    int histS[NBS];                   // slow-path histogram
    int bposS[NBS];
    int rsum[1024];                   // suffix sums (shared fast/slow)
    int wred[33];
    int wcnt[32 * NCLS];
    int wof[32 * NCLS];
    int ccnt[NCLS];
    float rbx1[1024], rby1[1024], rbx2[1024], rby2[1024];
    float sx1[1024], sy1[1024], sx2[1024], sy2[1024], sar[1024];
    float ssc[1024];
    int slb[1024];
    int clist[NCLS * MAXK];
    int keepf[1024];
    int wscan[33];
    int n_high, cstar, mcnt, smax;
};

__device__ __forceinline__ int bucket_fast(unsigned sb) {
    return min((int)((sb - B9OFF) >> 11), NBF - 1);
}
__device__ __forceinline__ int bucket_slow(unsigned sb) {
    return min((int)((sb - B2OFF) >> 12), NBS - 1);
}

// Scan: conf>0.9 prefilter, warp-cooperative scoring. Emits only the fast-bin
// histogram (all s>0.9) and the dense high tier (s>0.96). No block syncs.
__global__ void scan_kernel(const float* __restrict__ preds) {
    cudaTriggerProgrammaticLaunchCompletion();
    int b = blockIdx.y;
    int a0 = blockIdx.x * 256 + threadIdx.x;
    int lane = threadIdx.x & 31;
    bool inb = a0 < ANCH;
    float conf0 = inb ? preds[((size_t)b * ANCH + a0) * ROW + 4] : 0.0f;
    unsigned m = __ballot_sync(FULLM, inb && (conf0 > PRE_THRESH));
    while (m) {
        int src = __ffs(m) - 1;
        m &= m - 1;
        int a = __shfl_sync(FULLM, a0, src);
        float conf = __shfl_sync(FULLM, conf0, src);
        const float* row = preds + ((size_t)b * ANCH + a) * ROW;
        float b0 = row[0], b1 = row[1], b2 = row[2], b3 = row[3];
#pragma unroll
        for (int part = 0; part < 3; part++) {
            int k = part * 32 + lane;
            float p = (k < NCLS) ? row[5 + k] : 0.0f;
            float s = __fmul_rn(p, conf);
            if (k < NCLS && s > PRE_THRESH) {
                unsigned sb = __float_as_uint(s);
                atomicAdd(&g_hist[b][bucket_fast(sb)], 1);
                if (s > HI_THRESH) {
                    int hp = atomicAdd(&g_hcnt[b], 1);
                    if (hp < HCAP) {
                        unsigned flat = (unsigned)a * 80u + (unsigned)k;
                        g_hkey[b][hp] =
                            ((unsigned long long)sb << 32) |
                            (unsigned long long)(~flat);
                        g_hbox[b][hp] = make_float4(b0, b1, b2, b3);
                    }
                }
            }
        }
    }
}

// Inclusive suffix sums of per-thread value v -> sm.rsum (block-wide)
__device__ __forceinline__ void suffix_scan(SMF& sm, int v, int tid,
                                            int lane, int wid) {
    int vs = v;
#pragma unroll
    for (int off = 1; off < 32; off <<= 1) {
        int t = __shfl_down_sync(FULLM, vs, off);
        if (lane + off < 32) vs += t;
    }
    if (lane == 0) sm.wred[wid] = vs;
    __syncthreads();
    if (wid == 0) {
        int w = sm.wred[lane];
        __syncwarp();
#pragma unroll
        for (int off = 1; off < 32; off <<= 1) {
            int t = __shfl_down_sync(FULLM, w, off);
            if (lane + off < 32) w += t;
        }
        sm.wred[lane] = w;  // inclusive suffix over warp totals
    }
    __syncthreads();
    sm.rsum[tid] = vs + ((wid < 31) ? sm.wred[wid + 1] : 0);
    __syncthreads();
}

__global__ void __launch_bounds__(1024, 1)
final_kernel(const float* __restrict__ preds, float* __restrict__ out) {
    extern __shared__ char smc[];
    SMF& sm = *(SMF*)smc;
    int b = blockIdx.x;
    int tid = threadIdx.x;
    int lane = tid & 31;
    int wid = tid >> 5;

    // ---- dependency-free init ----
    sm.ssc[tid] = -1.0f;    // matches reference semantics for empty slots
    sm.slb[tid] = 0;
    for (int i = tid; i < 32 * NCLS; i += 1024) sm.wcnt[i] = 0;
    sm.keepf[tid] = 0;
    if (tid == 0) { sm.cstar = NBF; sm.mcnt = 0; sm.smax = 0; }

    // ---- wait for scan_kernel's writes, then ingest ----
    cudaGridDependencySynchronize();
    int v = g_hist[b][tid];   // exactly one fast bin per thread
    sm.histF[tid] = v;
    g_hist[b][tid] = 0;
    if (tid == 0) {
        sm.n_high = g_hcnt[b];
        g_hcnt[b] = 0;
    }
    __syncthreads();

    // ---- suffix over 1024 bins, cutoff, bases ----
    suffix_scan(sm, v, tid, lane, wid);
    if (sm.rsum[tid] >= PRE && (tid == 1023 || sm.rsum[tid + 1] < PRE)) {
        sm.cstar = tid;
        sm.mcnt = sm.rsum[tid];
    }
    sm.bposF[tid] = (tid < 1023) ? sm.rsum[tid + 1] : 0;  // bin base
    __syncthreads();

    bool slow = (sm.rsum[0] < PRE) || (sm.cstar < HBIN) ||
                (sm.n_high > HCAP);

    if (!slow) {
        int cs = sm.cstar;
        int nh = sm.n_high;

        // ---- compact dense high tier into bin regions ----
        for (int i = tid; i < nh; i += 1024) {
            unsigned long long key = g_hkey[b][i];
            int bk = bucket_fast((unsigned)(key >> 32));
            if (bk >= cs) {
                int pos = atomicAdd(&sm.bposF[bk], 1);
                if (pos < SORTN) {
                    sm.keys[pos] = key;
                    sm.aux[pos] = i;
                }
            }
        }
        __syncthreads();

        // ---- exact rank; write score/label/box at rank directly ----
        unsigned lmxb = 0;
        int mC = min(sm.mcnt, SORTN);
#pragma unroll
        for (int it = 0; it < 2; it++) {
            int idx = tid + it * 1024;
            if (idx < mC) {
                unsigned long long key = sm.keys[idx];
                int bk = bucket_fast((unsigned)(key >> 32));
                int endv = sm.bposF[bk];
                int base = endv - sm.histF[bk];
                int end = min(endv, SORTN);
                int rank = base;
                for (int j = base; j < end; j++)
                    rank += (sm.keys[j] > key);
                if (rank < PRE) {
                    unsigned flat = ~((unsigned)(key & 0xffffffffull));
                    sm.ssc[rank] = __uint_as_float((unsigned)(key >> 32));
                    sm.slb[rank] = (int)(flat - (flat / 80u) * 80u);
                    float4 bx = g_hbox[b][sm.aux[idx]];
                    sm.rbx1[rank] = bx.x; sm.rby1[rank] = bx.y;
                    sm.rbx2[rank] = bx.z; sm.rby2[rank] = bx.w;
                    float mx = fmaxf(fmaxf(bx.x, bx.y), fmaxf(bx.z, bx.w));
                    lmxb = max(lmxb, (unsigned)__float_as_int(mx));
                }
            }
        }
#pragma unroll
        for (int off = 16; off > 0; off >>= 1)
            lmxb = max(lmxb, __shfl_xor_sync(FULLM, lmxb, off));
        if (lane == 0) atomicMax(&sm.smax, (int)lmxb);
        __syncthreads();
    } else {
        // ======= slow path (exactness-gated; statistically never) ========
#pragma unroll
        for (int q = 0; q < GRPS; q++) sm.histS[tid * GRPS + q] = 0;
        if (tid == 0) { sm.cstar = NBS; sm.mcnt = 0; }
        __syncthreads();
        const float* bp = preds + (size_t)b * ANCH * ROW;
        for (int i = tid; i < NSC; i += 1024) {
            int a = i / 80, k = i - a * 80;
            float s = __fmul_rn(bp[(size_t)a * ROW + 5 + k],
                                bp[(size_t)a * ROW + 4]);
            if (s > CONF_THRESH)
                atomicAdd(&sm.histS[bucket_slow(__float_as_uint(s))], 1);
        }
        __syncthreads();
        {
            int vs = 0;
#pragma unroll
            for (int q = 0; q < GRPS; q++) vs += sm.histS[tid * GRPS + q];
            suffix_scan(sm, vs, tid, lane, wid);
        }
        int t_target = min(PRE, sm.rsum[0]);
        if (t_target > 0 && sm.rsum[tid] >= t_target &&
            (tid == 1023 || sm.rsum[tid + 1] < t_target)) {
            int acc = (tid < 1023) ? sm.rsum[tid + 1] : 0;
            for (int bk = tid * GRPS + GRPS - 1; bk >= tid * GRPS; bk--) {
                acc += sm.histS[bk];
                if (acc >= t_target) {
                    sm.cstar = bk;
                    sm.mcnt = acc;
                    break;
                }
            }
        }
        {
            int run = (tid < 1023) ? sm.rsum[tid + 1] : 0;
            for (int q = GRPS - 1; q >= 0; q--) {
                sm.bposS[tid * GRPS + q] = run;
                run += sm.histS[tid * GRPS + q];
            }
        }
        __syncthreads();
        int cs = sm.cstar;
        for (int i = tid; i < NSC; i += 1024) {
            int a = i / 80, k = i - a * 80;
            float s = __fmul_rn(bp[(size_t)a * ROW + 5 + k],
                                bp[(size_t)a * ROW + 4]);
            if (s > CONF_THRESH) {
                int bk = bucket_slow(__float_as_uint(s));
                if (bk >= cs) {
                    int pos = atomicAdd(&sm.bposS[bk], 1);
                    if (pos < SORTN) {
                        sm.keys[pos] =
                            ((unsigned long long)__float_as_uint(s) << 32) |
                            (unsigned long long)(~(unsigned)i);
                        sm.aux[pos] = i;
                    }
                }
            }
        }
        __syncthreads();
        int mC = min(sm.mcnt, SORTN);
#pragma unroll
        for (int it = 0; it < 2; it++) {
            int idx = tid + it * 1024;
            if (idx < mC) {
                unsigned long long key = sm.keys[idx];
                int bk = bucket_slow((unsigned)(key >> 32));
                int endv = sm.bposS[bk];
                int base = endv - sm.histS[bk];
                int end = min(endv, SORTN);
                int rank = base;
                for (int j = base; j < end; j++)
                    rank += (sm.keys[j] > key);
                if (rank < PRE) {
                    unsigned flat = (unsigned)sm.aux[idx];
                    sm.ssc[rank] = __uint_as_float((unsigned)(key >> 32));
                    sm.slb[rank] = (int)(flat - (flat / 80u) * 80u);
                    const float* row = bp + (size_t)(flat / 80u) * ROW;
                    float b0 = row[0], b1 = row[1];
                    float b2 = row[2], b3 = row[3];
                    sm.rbx1[rank] = b0; sm.rby1[rank] = b1;
                    sm.rbx2[rank] = b2; sm.rby2[rank] = b3;
                    float mx = fmaxf(fmaxf(b0, b1), fmaxf(b2, b3));
                    atomicMax(&sm.smax, __float_as_int(mx));
                }
            }
        }
        __syncthreads();
        // ranks >= mcnt keep init values: ssc=-1, slb=0 (matches reference)
    }

    // ---- class shift (bit-exact reference arithmetic) ----
    {
        float M = __int_as_float(sm.smax);
        float shb = __fadd_rn(M, 1.0f);
        float sh = __fmul_rn((float)sm.slb[tid], shb);
        float x1 = __fadd_rn(sm.rbx1[tid], sh);
        float y1 = __fadd_rn(sm.rby1[tid], sh);
        float x2 = __fadd_rn(sm.rbx2[tid], sh);
        float y2 = __fadd_rn(sm.rby2[tid], sh);
        sm.sx1[tid] = x1; sm.sy1[tid] = y1; sm.sx2[tid] = x2; sm.sy2[tid] = y2;
        sm.sar[tid] = __fmul_rn(fmaxf(__fsub_rn(x2, x1), 0.0f),
                                fmaxf(__fsub_rn(y2, y1), 0.0f));
    }

    // ---- stable per-class grouping: match_any + cross-warp shfl scan ----
    int mylbl = (tid < PRE) ? sm.slb[tid] : -1;
    unsigned grpm = __match_any_sync(FULLM, mylbl);
    int wrank = __popc(grpm & ((1u << lane) - 1u));
    if (tid < PRE && wrank == 0)
        sm.wcnt[wid * NCLS + mylbl] = __popc(grpm);
    __syncthreads();
    for (int c = wid; c < NCLS; c += 32) {
        int vv = sm.wcnt[lane * NCLS + c];
        int x = vv;
#pragma unroll
        for (int off = 1; off < 32; off <<= 1) {
            int t = __shfl_up_sync(FULLM, x, off);
            if (lane >= off) x += t;
        }
        sm.wof[lane * NCLS + c] = x - vv;  // exclusive
        if (lane == 31) sm.ccnt[c] = x;
    }
    __syncthreads();
    if (tid < PRE) {
        int pos = sm.wof[wid * NCLS + mylbl] + wrank;
        if (pos < MAXK) sm.clist[mylbl * MAXK + pos] = tid;
    }
    __syncthreads();

    // ---- warp-parallel per-class greedy NMS (one warp per class) ----
    for (int c = wid; c < NCLS; c += 32) {
        int kc = min(sm.ccnt[c], MAXK);
        if (kc == 0) continue;
        if (kc <= 32) {
            int j1 = (lane < kc) ? sm.clist[c * MAXK + lane] : 0;
            float x1a = sm.sx1[j1], y1a = sm.sy1[j1];
            float x2a = sm.sx2[j1], y2a = sm.sy2[j1], ara = sm.sar[j1];
            unsigned keep =
                __ballot_sync(FULLM, lane < kc && sm.ssc[j1] > CONF_THRESH);
            for (int ii = 0; ii < kc; ii++) {
                if (!((keep >> ii) & 1u)) continue;  // warp-uniform
                float px1 = __shfl_sync(FULLM, x1a, ii);
                float py1 = __shfl_sync(FULLM, y1a, ii);
                float px2 = __shfl_sync(FULLM, x2a, ii);
                float py2 = __shfl_sync(FULLM, y2a, ii);
                float par = __shfl_sync(FULLM, ara, ii);
                float iw = fmaxf(__fsub_rn(fminf(px2, x2a), fmaxf(px1, x1a)), 0.0f);
                float ih = fmaxf(__fsub_rn(fminf(py2, y2a), fmaxf(py1, y1a)), 0.0f);
                float inter = __fmul_rn(iw, ih);
                float den = __fadd_rn(__fsub_rn(__fadd_rn(par, ara), inter), 1e-7f);
                bool s1 = (lane > ii) && (lane < kc) &&
                          (__fdiv_rn(inter, den) > NMS_THRESH);
                keep &= ~__ballot_sync(FULLM, s1);
            }
            if (lane < kc) sm.keepf[j1] = (int)((keep >> lane) & 1u);
        } else {
            int i1 = lane, i2 = lane + 32;
            int j1 = sm.clist[c * MAXK + i1];
            int j2 = (i2 < kc) ? sm.clist[c * MAXK + i2] : 0;
            float x1a = sm.sx1[j1], y1a = sm.sy1[j1];
            float x2a = sm.sx2[j1], y2a = sm.sy2[j1], ara = sm.sar[j1];
            float x1b = sm.sx1[j2], y1b = sm.sy1[j2];
            float x2b = sm.sx2[j2], y2b = sm.sy2[j2], arb = sm.sar[j2];
            unsigned m1 = __ballot_sync(FULLM, sm.ssc[j1] > CONF_THRESH);
            unsigned m2 =
                __ballot_sync(FULLM, i2 < kc && sm.ssc[j2] > CONF_THRESH);
            unsigned long long keep =
                (unsigned long long)m1 | ((unsigned long long)m2 << 32);
            for (int ii = 0; ii < kc; ii++) {
                if (!((keep >> ii) & 1ull)) continue;
                int src = ii & 31;
                bool hi = ii >= 32;
                float px1 = __shfl_sync(FULLM, hi ? x1b : x1a, src);
                float py1 = __shfl_sync(FULLM, hi ? y1b : y1a, src);
                float px2 = __shfl_sync(FULLM, hi ? x2b : x2a, src);
                float py2 = __shfl_sync(FULLM, hi ? y2b : y2a, src);
                float par = __shfl_sync(FULLM, hi ? arb : ara, src);
                float iw1 = fmaxf(__fsub_rn(fminf(px2, x2a), fmaxf(px1, x1a)), 0.0f);
                float ih1 = fmaxf(__fsub_rn(fminf(py2, y2a), fmaxf(py1, y1a)), 0.0f);
                float it1 = __fmul_rn(iw1, ih1);
                float dn1 = __fadd_rn(__fsub_rn(__fadd_rn(par, ara), it1), 1e-7f);
                bool s1 = (i1 > ii) && (__fdiv_rn(it1, dn1) > NMS_THRESH);
                float iw2 = fmaxf(__fsub_rn(fminf(px2, x2b), fmaxf(px1, x1b)), 0.0f);
                float ih2 = fmaxf(__fsub_rn(fminf(py2, y2b), fmaxf(py1, y1b)), 0.0f);
                float it2 = __fmul_rn(iw2, ih2);
                float dn2 = __fadd_rn(__fsub_rn(__fadd_rn(par, arb), it2), 1e-7f);
                bool s2 = (i2 > ii) && (i2 < kc) &&
                          (__fdiv_rn(it2, dn2) > NMS_THRESH);
                unsigned b1 = __ballot_sync(FULLM, s1);
                unsigned b2 = __ballot_sync(FULLM, s2);
                keep &= ~((unsigned long long)b1 |
                          ((unsigned long long)b2 << 32));
            }
            sm.keepf[j1] = (int)((keep >> i1) & 1ull);
            if (i2 < kc) sm.keepf[j2] = (int)((keep >> i2) & 1ull);
        }
    }
    __syncthreads();

    // ---- keep-flag prefix sum (warp shuffles) ----
    int myscan, total;
    {
        int p = sm.keepf[tid];
#pragma unroll
        for (int off = 1; off < 32; off <<= 1) {
            int t = __shfl_up_sync(FULLM, p, off);
            if (lane >= off) p += t;
        }
        if (lane == 31) sm.wscan[wid] = p;
        __syncthreads();
        if (wid == 0) {
            int w = sm.wscan[lane];
            __syncwarp();
#pragma unroll
            for (int off = 1; off < 32; off <<= 1) {
                int t = __shfl_up_sync(FULLM, w, off);
                if (lane >= off) w += t;
            }
            sm.wscan[lane] = w;
        }
        __syncthreads();
        int base = (wid > 0) ? sm.wscan[wid - 1] : 0;
        myscan = base + p;
        total = sm.wscan[31];
    }

    // ---- emit top-300 ----
    float* ob = out;                               // [16][300][4]
    float* os = out + (size_t)BATCH * MAXDET * 4;  // [16][300]
    float* ol = out + (size_t)BATCH * MAXDET * 5;  // [16][300] labels as f32

    if (tid < PRE && sm.keepf[tid]) {
        int m = myscan - 1;
        if (m < MAXDET) {
            float* p = ob + ((size_t)b * MAXDET + m) * 4;
            p[0] = sm.rbx1[tid]; p[1] = sm.rby1[tid];
            p[2] = sm.rbx2[tid]; p[3] = sm.rby2[tid];
            os[b * MAXDET + m] = sm.ssc[tid];
            ol[b * MAXDET + m] = (float)sm.slb[tid];
        }
    }
    for (int m = tid; m < MAXDET; m += 1024) {
        if (m >= total) {
            float* p = ob + ((size_t)b * MAXDET + m) * 4;
            p[0] = 0.0f; p[1] = 0.0f; p[2] = 0.0f; p[3] = 0.0f;
            os[b * MAXDET + m] = 0.0f;
            ol[b * MAXDET + m] = -1.0f;
        }
    }
}

extern "C" void kernel_launch(void* const* d_in, const int* in_sizes, int n_in,
                              void* d_out, int out_size) {
    (void)in_sizes; (void)n_in; (void)out_size;
    const float* preds = (const float*)d_in[0];
    float* out = (float*)d_out;

    cudaFuncSetAttribute(final_kernel,
                         cudaFuncAttributeMaxDynamicSharedMemorySize,
                         (int)sizeof(SMF));

    scan_kernel<<<dim3(ABLK, BATCH), 256>>>(preds);

    cudaLaunchConfig_t cfg = {};
    cfg.gridDim = dim3(BATCH, 1, 1);
    cfg.blockDim = dim3(1024, 1, 1);
    cfg.dynamicSmemBytes = sizeof(SMF);
    cfg.stream = 0;
    cudaLaunchAttribute at[1];
    at[0].id = cudaLaunchAttributeProgrammaticStreamSerialization;
    at[0].val.programmaticStreamSerializationAllowed = 1;
    cfg.attrs = at;
    cfg.numAttrs = 1;
    cudaLaunchKernelEx(&cfg, final_kernel, preds, out);
}